// round 1
// baseline (speedup 1.0000x reference)
#include <cuda_runtime.h>

#define NQ   4
#define DIM  16
#define NL   2
#define EDIM 512
#define TOK_PER_BLOCK 64
#define NTHREADS 256
#define NTOKENS (512*128)

__global__ __launch_bounds__(NTHREADS)
void qlayer_fused(const float* __restrict__ x,
                  const float* __restrict__ qw,
                  const float* __restrict__ Wq,
                  const float* __restrict__ bq,
                  const float* __restrict__ Wc,
                  const float* __restrict__ bc,
                  float* __restrict__ out)
{
    __shared__ float4 sWq[NQ][EDIM/4];    // Wq[q][e], vectorized
    __shared__ float4 sWcT[NQ][EDIM/4];   // Wc transposed: [q][e]
    __shared__ float4 sbc4[EDIM/4];
    __shared__ float2 sdiag[NL][DIM];     // combined CRZ-ring diagonal per layer
    __shared__ float2 srys[NL][NQ];       // (cos, sin) of theta/2 per RY
    __shared__ float  sbq[NQ];
    __shared__ float4 sqin[TOK_PER_BLOCK];
    __shared__ float4 sqout[TOK_PER_BLOCK];

    const int tid  = threadIdx.x;
    const int lane = tid & 31;
    const int warp = tid >> 5;

    // ---- Stage weights / constants into shared ----
    for (int i = tid; i < NQ*EDIM/4; i += NTHREADS)
        ((float4*)sWq)[i] = ((const float4*)Wq)[i];
    {
        float* sWcTf = (float*)sWcT;
        for (int e = tid; e < EDIM; e += NTHREADS) {
            float4 r = ((const float4*)Wc)[e];   // Wc row e = 4 contiguous floats
            sWcTf[0*EDIM + e] = r.x;
            sWcTf[1*EDIM + e] = r.y;
            sWcTf[2*EDIM + e] = r.z;
            sWcTf[3*EDIM + e] = r.w;
        }
    }
    for (int i = tid; i < EDIM/4; i += NTHREADS)
        sbc4[i] = ((const float4*)bc)[i];
    if (tid < NQ) sbq[tid] = bq[tid];

    // Combined CRZ-ring diagonal: all CRZ gates are diagonal, so fold the
    // whole ring of layer l into one diag of phases exp(i*ang_k).
    if (tid < NL*DIM) {
        int l = tid >> 4, k = tid & 15;
        float ang = 0.f;
        #pragma unroll
        for (int i = 0; i < NQ; i++) {
            int cb = (k >> (NQ-1-i)) & 1;                         // control bit
            int tb = (k >> (NQ-1-((i+1)&(NQ-1)))) & 1;            // target bit
            if (cb) ang += 0.5f * qw[l*2*NQ + i] * (float)(2*tb - 1);
        }
        float sn, cs; sincosf(ang, &sn, &cs);
        sdiag[l][k] = make_float2(cs, sn);
    }
    if (tid >= 32 && tid < 32 + NL*NQ) {
        int t = tid - 32, l = t >> 2, i = t & 3;
        float sn, cs; sincosf(0.5f * qw[l*2*NQ + NQ + i], &sn, &cs);
        srys[l][i] = make_float2(cs, sn);
    }
    __syncthreads();

    // ---- Phase 1: q_in = x . Wq^T + bq (warp-cooperative, coalesced) ----
    const int tok0 = blockIdx.x * TOK_PER_BLOCK + warp * 8;
    float acc[8][4];
    #pragma unroll
    for (int t = 0; t < 8; t++)
        #pragma unroll
        for (int q = 0; q < 4; q++) acc[t][q] = 0.f;

    #pragma unroll
    for (int chunk = 0; chunk < 4; chunk++) {
        int j4 = chunk*32 + lane;
        float4 w0 = sWq[0][j4], w1 = sWq[1][j4], w2 = sWq[2][j4], w3 = sWq[3][j4];
        #pragma unroll
        for (int t = 0; t < 8; t++) {
            float4 xv = ((const float4*)x)[(tok0 + t)*(EDIM/4) + j4];
            acc[t][0] += xv.x*w0.x + xv.y*w0.y + xv.z*w0.z + xv.w*w0.w;
            acc[t][1] += xv.x*w1.x + xv.y*w1.y + xv.z*w1.z + xv.w*w1.w;
            acc[t][2] += xv.x*w2.x + xv.y*w2.y + xv.z*w2.z + xv.w*w2.w;
            acc[t][3] += xv.x*w3.x + xv.y*w3.y + xv.z*w3.z + xv.w*w3.w;
        }
    }
    #pragma unroll
    for (int t = 0; t < 8; t++) {
        #pragma unroll
        for (int off = 16; off; off >>= 1) {
            acc[t][0] += __shfl_xor_sync(0xffffffffu, acc[t][0], off);
            acc[t][1] += __shfl_xor_sync(0xffffffffu, acc[t][1], off);
            acc[t][2] += __shfl_xor_sync(0xffffffffu, acc[t][2], off);
            acc[t][3] += __shfl_xor_sync(0xffffffffu, acc[t][3], off);
        }
        if (lane == 0)
            sqin[warp*8 + t] = make_float4(acc[t][0]+sbq[0], acc[t][1]+sbq[1],
                                           acc[t][2]+sbq[2], acc[t][3]+sbq[3]);
    }
    __syncthreads();

    // ---- Phase 2: 4-qubit circuit, one thread per token (no redundancy) ----
    if (tid < TOK_PER_BLOCK) {
        float4 qin = sqin[tid];
        float c[4], s[4];
        __sincosf(0.5f*qin.x, &s[0], &c[0]);
        __sincosf(0.5f*qin.y, &s[1], &c[1]);
        __sincosf(0.5f*qin.z, &s[2], &c[2]);
        __sincosf(0.5f*qin.w, &s[3], &c[3]);

        // AngleEmbedding(RX) product state: amp_k = prod(c/s) * (-i)^popcount(k)
        float2 st[DIM];
        #pragma unroll
        for (int k = 0; k < DIM; k++) {
            float m = 1.f;
            int p = 0;
            #pragma unroll
            for (int w = 0; w < NQ; w++) {
                if ((k >> (NQ-1-w)) & 1) { m *= s[w]; p++; }
                else                     { m *= c[w]; }
            }
            float re, im;
            switch (p & 3) {               // constant-folded per k
                case 0:  re =  m; im = 0.f; break;
                case 1:  re = 0.f; im = -m; break;
                case 2:  re = -m; im = 0.f; break;
                default: re = 0.f; im =  m; break;
            }
            st[k] = make_float2(re, im);
        }

        #pragma unroll
        for (int l = 0; l < NL; l++) {
            // fused CRZ ring (diagonal)
            #pragma unroll
            for (int k = 0; k < DIM; k++) {
                float2 d = sdiag[l][k];
                float re = st[k].x*d.x - st[k].y*d.y;
                float im = st[k].x*d.y + st[k].y*d.x;
                st[k].x = re; st[k].y = im;
            }
            // RY on each qubit (butterflies, stride = bit position)
            #pragma unroll
            for (int i = 0; i < NQ; i++) {
                float2 cs = srys[l][i];
                const int S = 1 << (NQ-1-i);
                #pragma unroll
                for (int k = 0; k < DIM; k++) {
                    if (k & S) continue;
                    float2 a0 = st[k], a1 = st[k|S];
                    st[k].x   = cs.x*a0.x - cs.y*a1.x;
                    st[k].y   = cs.x*a0.y - cs.y*a1.y;
                    st[k|S].x = cs.y*a0.x + cs.x*a1.x;
                    st[k|S].y = cs.y*a0.y + cs.x*a1.y;
                }
            }
        }

        // PauliZ expectation values from probabilities
        float z0=0.f, z1=0.f, z2=0.f, z3=0.f;
        #pragma unroll
        for (int k = 0; k < DIM; k++) {
            float p = st[k].x*st[k].x + st[k].y*st[k].y;
            z0 += (k & 8) ? -p : p;
            z1 += (k & 4) ? -p : p;
            z2 += (k & 2) ? -p : p;
            z3 += (k & 1) ? -p : p;
        }
        sqout[tid] = make_float4(z0, z1, z2, z3);
    }
    __syncthreads();

    // ---- Phase 3: out = q_out . Wc^T + bc (coalesced float4 stores) ----
    float4 qo[8];
    #pragma unroll
    for (int t = 0; t < 8; t++) qo[t] = sqout[warp*8 + t];

    #pragma unroll
    for (int chunk = 0; chunk < 4; chunk++) {
        int e4 = chunk*32 + lane;
        float4 w0 = sWcT[0][e4], w1 = sWcT[1][e4], w2 = sWcT[2][e4], w3 = sWcT[3][e4];
        float4 b  = sbc4[e4];
        #pragma unroll
        for (int t = 0; t < 8; t++) {
            float4 o;
            o.x = b.x + qo[t].x*w0.x + qo[t].y*w1.x + qo[t].z*w2.x + qo[t].w*w3.x;
            o.y = b.y + qo[t].x*w0.y + qo[t].y*w1.y + qo[t].z*w2.y + qo[t].w*w3.y;
            o.z = b.z + qo[t].x*w0.z + qo[t].y*w1.z + qo[t].z*w2.z + qo[t].w*w3.z;
            o.w = b.w + qo[t].x*w0.w + qo[t].y*w1.w + qo[t].z*w2.w + qo[t].w*w3.w;
            ((float4*)out)[(tok0 + t)*(EDIM/4) + e4] = o;
        }
    }
}

extern "C" void kernel_launch(void* const* d_in, const int* in_sizes, int n_in,
                              void* d_out, int out_size) {
    const float* x  = (const float*)d_in[0];
    const float* qw = (const float*)d_in[1];
    const float* Wq = (const float*)d_in[2];
    const float* bq = (const float*)d_in[3];
    const float* Wc = (const float*)d_in[4];
    const float* bc = (const float*)d_in[5];
    float* out = (float*)d_out;

    dim3 grid(NTOKENS / TOK_PER_BLOCK);   // 1024 blocks x 64 tokens
    qlayer_fused<<<grid, NTHREADS>>>(x, qw, Wq, bq, Wc, bc, out);
}